// round 14
// baseline (speedup 1.0000x reference)
#include <cuda_runtime.h>

// Potential_6347961663538 — Gaussian form-factor splatting onto a 128x128 grid.
//
// out[b,i,j] = sum_a sum_f (ff_a·4π/ff_b)[a,f] *
//              exp(-π·(4π/ff_b)[a,f] · ((j-64-c0[b,a])² + (i-64-c1[b,a])²))
//
// ALGORITHM: π·invb = 4π²/ff_b >= 19.74 (ff_b in [0.5,2]), so any term with
// per-axis |d| > 3.5 underflows fp32 exp to exactly 0 — identical to the
// zeros the reference itself adds. A 7x7 window around round(coord)
// reproduces every nonzero fp32 term: 671M dense terms -> ~401K (~1700x).
//
// R14: 2 atoms per warp, 512 blocks x 256 threads. Halves CTA count
// (distribution/launch fixed cost) and amortizes the serial per-warp
// LDG->RCP->SHFL constant chain over two atoms (coord/ff loads for both
// atoms issued up-front, MLP=6). Job-1 range guard dropped: for pixel ids
// 49..63 the row distance is >=3.5 so the EX2 underflows to exactly 0.0f
// and the s!=0 predicate rejects — mathematically identical.
//
// Context: bench total has a ~8.5-8.7us per-replay floor (12 rounds of
// evidence; 1-node vs 2-node graphs identical) with ~±0.25us noise; kernel
// time is the only remaining lever.

#define SIDELEN 128
#define NATOM   2048
#define NB      4
#define NF      5
#define RAD     3
#define WIN     7
#define WPB     8            // warps per block
#define APW     2            // atoms per warp

__device__ __forceinline__ float ex2_approx(float x) {
    float r;
    asm("ex2.approx.f32 %0, %1;" : "=f"(r) : "f"(x));
    return r;
}

__global__ void __launch_bounds__(WPB * 32) potential_scatter_kernel(
    const float* __restrict__ coords,   // [NB, NATOM, 3]
    const float* __restrict__ ff_a,     // [NATOM, NF]
    const float* __restrict__ ff_b,     // [NATOM, NF]
    float* __restrict__ out)            // [NB, SIDELEN, SIDELEN]
{
    const int gw   = blockIdx.x * WPB + (threadIdx.x >> 5);  // 0..4095
    const int lane = threadIdx.x & 31;
    const int g0   = gw * APW;                // global atom id of atom 0
    const int b    = g0 >> 11;                // batch (pairs never straddle)
    const int a0   = g0 & (NATOM - 1);        // ff index of atom 0

    // ---- up-front loads: coords of both atoms (MLP=4) + ff pairs ----
    const float c0x = __ldg(&coords[(g0 + 0) * 3 + 0]);
    const float c0y = __ldg(&coords[(g0 + 0) * 3 + 1]);
    const float c1x = __ldg(&coords[(g0 + 1) * 3 + 0]);
    const float c1y = __ldg(&coords[(g0 + 1) * 3 + 1]);

    // lanes 0..9: (atom k = lane/5, factor f = lane%5); one divide each.
    float p2 = 0.0f, cf = 0.0f;
    if (lane < APW * NF) {
        const int k = lane / NF;
        const int f = lane - k * NF;
        const float inv = __fdividef(1.0f, __ldg(&ff_b[(a0 + k) * NF + f]));
        p2 = -56.9553183f * inv;                              // -(4π²·log2e)/ff_b
        cf = __ldg(&ff_a[(a0 + k) * NF + f]) * 12.56637061f * inv;  // ff_a·4π/ff_b
    }

    float* outb = out + (b << 14);

    // Two window pixels per lane: p = lane and lane+32.
    const int wi0 = lane / WIN, wj0 = lane - wi0 * WIN;
    const int pp  = lane + 32;
    const int wi1 = pp / WIN,   wj1 = pp - wi1 * WIN;   // wi1 in [1,9]; rows
                                                        // >=7 underflow to 0.

    #pragma unroll
    for (int k = 0; k < APW; ++k) {
        const float cx = k ? c1x : c0x;
        const float cy = k ? c1y : c0y;

        const float p20 = __shfl_sync(0xffffffffu, p2, k * NF + 0);
        const float p21 = __shfl_sync(0xffffffffu, p2, k * NF + 1);
        const float p22 = __shfl_sync(0xffffffffu, p2, k * NF + 2);
        const float p23 = __shfl_sync(0xffffffffu, p2, k * NF + 3);
        const float p24 = __shfl_sync(0xffffffffu, p2, k * NF + 4);
        const float cf0 = __shfl_sync(0xffffffffu, cf, k * NF + 0);
        const float cf1 = __shfl_sync(0xffffffffu, cf, k * NF + 1);
        const float cf2 = __shfl_sync(0xffffffffu, cf, k * NF + 2);
        const float cf3 = __shfl_sync(0xffffffffu, cf, k * NF + 3);
        const float cf4 = __shfl_sync(0xffffffffu, cf, k * NF + 4);

        const int jc = __float2int_rn(cx);
        const int ic = __float2int_rn(cy);
        const float fx = (float)(jc - RAD) - cx;     // dx at window col 0
        const float fy = (float)(ic - RAD) - cy;     // dy at window row 0
        const int jb = jc + SIDELEN / 2 - RAD;
        const int ib = ic + SIDELEN / 2 - RAD;

        {   // job 0: pixel p = lane (0..31, rows 0..4)
            const float dx = fx + (float)wj0, dy = fy + (float)wi0;
            const float dd = fmaf(dx, dx, dy * dy);
            float s =            cf0 * ex2_approx(p20 * dd);
            s = fmaf(cf1, ex2_approx(p21 * dd), s);
            s = fmaf(cf2, ex2_approx(p22 * dd), s);
            s = fmaf(cf3, ex2_approx(p23 * dd), s);
            s = fmaf(cf4, ex2_approx(p24 * dd), s);
            const int i = ib + wi0, j = jb + wj0;
            if ((unsigned)i < SIDELEN && (unsigned)j < SIDELEN && s != 0.0f)
                atomicAdd(&outb[(i << 7) + j], s);
        }
        {   // job 1: pixel p = lane+32 (rows 4..9; rows>6 give s==0 exactly)
            const float dx = fx + (float)wj1, dy = fy + (float)wi1;
            const float dd = fmaf(dx, dx, dy * dy);
            float s =            cf0 * ex2_approx(p20 * dd);
            s = fmaf(cf1, ex2_approx(p21 * dd), s);
            s = fmaf(cf2, ex2_approx(p22 * dd), s);
            s = fmaf(cf3, ex2_approx(p23 * dd), s);
            s = fmaf(cf4, ex2_approx(p24 * dd), s);
            const int i = ib + wi1, j = jb + wj1;
            if ((unsigned)i < SIDELEN && (unsigned)j < SIDELEN && s != 0.0f)
                atomicAdd(&outb[(i << 7) + j], s);
        }
    }
}

extern "C" void kernel_launch(void* const* d_in, const int* in_sizes, int n_in,
                              void* d_out, int out_size) {
    const float* coords = (const float*)d_in[0];
    const float* ff_a   = (const float*)d_in[1];
    const float* ff_b   = (const float*)d_in[2];
    float* out = (float*)d_out;

    cudaMemsetAsync(out, 0, (size_t)out_size * sizeof(float));
    potential_scatter_kernel<<<(NB * NATOM) / (WPB * APW), WPB * 32>>>(
        coords, ff_a, ff_b, out);
}